// round 8
// baseline (speedup 1.0000x reference)
#include <cuda_runtime.h>
#include <cuda_fp16.h>

// ---------------------------------------------------------------------------
// MLMM electrostatics.
// E(p) = KE * q_v * ( q_u*chi - chi^3*(r.mu) + chi^5 * sum(O * Q') )
// with Q' = Q - (trQ/3) I (traceless), Q'22 = -(Q'00+Q'11).
//
// Gather record per ML atom: 32 bytes, 32B-aligned (ONE L2 sector):
//   float4 {q, mux, muy, muz} | 8 x fp16 {Q' components}
//
// R8: phase-split 2-pair tiles. TILE=512 pairs/block but only a 256-pair
// staging buffer (12 KB smem -> full occupancy, unlike R7's 25 KB). All six
// gather LDGs (both halves) are issued predicated & up-front, so each thread
// carries 2 independent gather chains across the phase-A staging window:
// doubled MLP at R6 occupancy.
// ---------------------------------------------------------------------------

#define NML_MAX 50000
#define KE_CONST 14.399645351950548f
#define CUTOFF_A 10.0f
#define BLK 256
#define TILE (2 * BLK)

// [2*u] : float4 {q, mu}; [2*u+1] : 8 fp16 Q' components
__device__ __align__(32) float4 g_packed[NML_MAX * 2];

__global__ void mlmm_prep_kernel(const float* __restrict__ q_ml,
                                 const float* __restrict__ mu,
                                 const float* __restrict__ Q,
                                 const float* __restrict__ e0,
                                 float* __restrict__ out,
                                 int nml) {
    int u = blockIdx.x * blockDim.x + threadIdx.x;
    if (u >= nml) return;

    out[u] = e0[u];

    float m0 = mu[3 * u + 0];
    float m1 = mu[3 * u + 1];
    float m2 = mu[3 * u + 2];

    float Qv[9];
#pragma unroll
    for (int k = 0; k < 9; k++) Qv[k] = Q[9 * u + k];
    float third_tr = (Qv[0] + Qv[4] + Qv[8]) * (1.0f / 3.0f);

    float t00 = Qv[0] - third_tr;
    float t11 = Qv[4] - third_tr;

    g_packed[2 * u + 0] = make_float4(q_ml[u], m0, m1, m2);

    __half2 h0 = __floats2half2_rn(t00,   Qv[1]);
    __half2 h1 = __floats2half2_rn(Qv[2], Qv[3]);
    __half2 h2 = __floats2half2_rn(t11,   Qv[5]);
    __half2 h3 = __floats2half2_rn(Qv[6], Qv[7]);

    uint4 packed;
    packed.x = *reinterpret_cast<unsigned int*>(&h0);
    packed.y = *reinterpret_cast<unsigned int*>(&h1);
    packed.z = *reinterpret_cast<unsigned int*>(&h2);
    packed.w = *reinterpret_cast<unsigned int*>(&h3);
    reinterpret_cast<uint4*>(g_packed)[2 * u + 1] = packed;
}

// stage cntS pairs starting at gmem pair index gbase into s_vec/s_out
__device__ __forceinline__ void stage_tile(float* s_vec, float* s_out,
                                           const float* __restrict__ vec,
                                           const float* __restrict__ outer,
                                           long long gbase, int cntS) {
    if (cntS == BLK) {
        const float4* v4 = (const float4*)(vec + 3 * gbase);
        float4*       sv = (float4*)s_vec;
#pragma unroll
        for (int t = threadIdx.x; t < BLK * 3 / 4; t += BLK) sv[t] = v4[t];

        const float4* o4 = (const float4*)(outer + 9 * gbase);
        float4*       so = (float4*)s_out;
#pragma unroll
        for (int t = threadIdx.x; t < BLK * 9 / 4; t += BLK) so[t] = o4[t];
    } else {
        for (int t = threadIdx.x; t < cntS * 3; t += BLK) s_vec[t] = vec[3 * gbase + t];
        for (int t = threadIdx.x; t < cntS * 9; t += BLK) s_out[t] = outer[9 * gbase + t];
    }
}

__device__ __forceinline__ float pair_energy(float d, const float4& p0,
                                             const uint4& ph, float qvke,
                                             const float* __restrict__ sv,
                                             const float* __restrict__ so) {
    float r0 = sv[0], r1 = sv[1], r2 = sv[2];
    float o00 = so[0], o01 = so[1], o02 = so[2];
    float o10 = so[3], o11 = so[4], o12 = so[5];
    float o20 = so[6], o21 = so[7], o22 = so[8];

    float chi  = __fdividef(1.0f, d);
    float chi2 = chi * chi;
    float chi3 = chi2 * chi;
    float chi5 = chi3 * chi2;

    float e = p0.x * chi;                                    // charge
    e -= chi3 * (r0 * p0.y + r1 * p0.z + r2 * p0.w);         // dipole

    float2 c0 = __half22float2(*reinterpret_cast<const __half2*>(&ph.x));
    float2 c1 = __half22float2(*reinterpret_cast<const __half2*>(&ph.y));
    float2 c2 = __half22float2(*reinterpret_cast<const __half2*>(&ph.z));
    float2 c3 = __half22float2(*reinterpret_cast<const __half2*>(&ph.w));

    float dot9 = c0.x * (o00 - o22)
               + c2.x * (o11 - o22)
               + c0.y * o01 + c1.x * o02 + c1.y * o10
               + c2.y * o12 + c3.x * o20 + c3.y * o21;
    e += chi5 * dot9;                                        // quadrupole

    return e * qvke;
}

__global__ void __launch_bounds__(BLK)
mlmm_pair_kernel(const float* __restrict__ dist,
                 const float* __restrict__ vec,
                 const float* __restrict__ outer,
                 const int* __restrict__ idx_u,
                 const int* __restrict__ idx_v,
                 const float* __restrict__ q_mm,
                 float* __restrict__ out,
                 int n) {
    __shared__ float s_vec[BLK * 3];
    __shared__ float s_out[BLK * 9];

    long long base = (long long)blockIdx.x * TILE;
    int cnt = n - (int)base;
    if (cnt > TILE) cnt = TILE;

    int lane = threadIdx.x;

    // ---- phase 0: issue per-thread loads for BOTH halves (predicated) ----
    long long i0 = base + lane;
    long long i1 = base + lane + BLK;

    float d0 = 1e30f, d1 = 1e30f;
    if (lane < cnt)        d0 = dist[i0];
    if (lane + BLK < cnt)  d1 = dist[i1];
    bool m0 = (d0 <= CUTOFF_A);
    bool m1 = (d1 <= CUTOFF_A);

    int u0 = 0, v0 = 0, u1 = 0, v1 = 0;
    if (m0) { u0 = idx_u[i0]; v0 = idx_v[i0]; }
    if (m1) { u1 = idx_u[i1]; v1 = idx_v[i1]; }

    float4 p00 = make_float4(0.f, 0.f, 0.f, 0.f);
    float4 p01 = make_float4(0.f, 0.f, 0.f, 0.f);
    uint4  ph0 = make_uint4(0u, 0u, 0u, 0u);
    uint4  ph1 = make_uint4(0u, 0u, 0u, 0u);
    float  qv0 = 0.f, qv1 = 0.f;
    if (m0) {
        p00 = g_packed[2 * u0 + 0];
        ph0 = reinterpret_cast<const uint4*>(g_packed)[2 * u0 + 1];
        qv0 = KE_CONST * __ldg(q_mm + v0);
    }
    if (m1) {
        p01 = g_packed[2 * u1 + 0];
        ph1 = reinterpret_cast<const uint4*>(g_packed)[2 * u1 + 1];
        qv1 = KE_CONST * __ldg(q_mm + v1);
    }

    // ---- phase A: stage pairs [0,256) ----
    int cntA = cnt < BLK ? cnt : BLK;
    stage_tile(s_vec, s_out, vec, outer, base, cntA);
    __syncthreads();

    if (m0) {
        float e = pair_energy(d0, p00, ph0, qv0,
                              s_vec + 3 * lane, s_out + 9 * lane);
        atomicAdd(out + u0, e);
    }

    // ---- phase B: stage pairs [256, cnt) ----
    int cntB = cnt - BLK;
    if (cntB > 0) {
        __syncthreads();  // everyone done reading phase-A smem
        stage_tile(s_vec, s_out, vec, outer, base + BLK, cntB);
        __syncthreads();

        if (m1) {
            float e = pair_energy(d1, p01, ph1, qv1,
                                  s_vec + 3 * lane, s_out + 9 * lane);
            atomicAdd(out + u1, e);
        }
    }
}

extern "C" void kernel_launch(void* const* d_in, const int* in_sizes, int n_in,
                              void* d_out, int out_size) {
    const float* q_ml  = (const float*)d_in[0];  // [NML]
    const float* q_mm  = (const float*)d_in[1];  // [NMM]
    const float* mu    = (const float*)d_in[2];  // [NML,3]
    const float* Q     = (const float*)d_in[3];  // [NML,3,3]
    const float* e0    = (const float*)d_in[4];  // [NML]
    const float* dist  = (const float*)d_in[5];  // [P]
    const float* vec   = (const float*)d_in[6];  // [P,3]
    const float* outer = (const float*)d_in[7];  // [P,3,3]
    const int*   idx_u = (const int*)d_in[8];    // [P] int32
    const int*   idx_v = (const int*)d_in[9];    // [P] int32

    float* out = (float*)d_out;

    int nml = in_sizes[0];
    int P   = in_sizes[5];

    {
        int threads = 256;
        int blocks  = (nml + threads - 1) / threads;
        mlmm_prep_kernel<<<blocks, threads>>>(q_ml, mu, Q, e0, out, nml);
    }
    {
        int blocks = (P + TILE - 1) / TILE;
        mlmm_pair_kernel<<<blocks, BLK>>>(dist, vec, outer, idx_u, idx_v,
                                          q_mm, out, P);
    }
}

// round 9
// speedup vs baseline: 1.0264x; 1.0264x over previous
#include <cuda_runtime.h>
#include <cuda_fp16.h>
#include <cstdint>

// ---------------------------------------------------------------------------
// MLMM electrostatics.
// E(p) = KE * q_v * ( q_u*chi - chi^3*(r.mu) + chi^5 * sum(O * Q') )
// with Q' = Q - (trQ/3) I (traceless), Q'22 = -(Q'00+Q'11).
//
// Gather record per ML atom: 32 bytes, 32B-aligned (ONE L2 sector):
//   float4 {q, mux, muy, muz} | 8 x fp16 {Q' components}
//
// R9: R6 thread structure (1 pair/thread, regs<=32, full occupancy), but the
// vec/outer tile staging moves from LDG+STS to TMA bulk copies
// (cp.async.bulk -> smem, mbarrier completion). That removes ~0.9 L1TEX
// wavefronts/pair (~21% of the wavefront budget); the TMA traffic rides the
// LTS/DRAM path which has headroom. Per-thread dist/idx/gather LDGs are
// issued before the mbarrier wait so gather latency hides under the TMA.
// ---------------------------------------------------------------------------

#define NML_MAX 50000
#define KE_CONST 14.399645351950548f
#define CUTOFF_A 10.0f
#define BLK 256

// [2*u] : float4 {q, mu}; [2*u+1] : 8 fp16 Q' components
__device__ __align__(32) float4 g_packed[NML_MAX * 2];

__global__ void mlmm_prep_kernel(const float* __restrict__ q_ml,
                                 const float* __restrict__ mu,
                                 const float* __restrict__ Q,
                                 const float* __restrict__ e0,
                                 float* __restrict__ out,
                                 int nml) {
    int u = blockIdx.x * blockDim.x + threadIdx.x;
    if (u >= nml) return;

    out[u] = e0[u];

    float m0 = mu[3 * u + 0];
    float m1 = mu[3 * u + 1];
    float m2 = mu[3 * u + 2];

    float Qv[9];
#pragma unroll
    for (int k = 0; k < 9; k++) Qv[k] = Q[9 * u + k];
    float third_tr = (Qv[0] + Qv[4] + Qv[8]) * (1.0f / 3.0f);

    float t00 = Qv[0] - third_tr;
    float t11 = Qv[4] - third_tr;

    g_packed[2 * u + 0] = make_float4(q_ml[u], m0, m1, m2);

    __half2 h0 = __floats2half2_rn(t00,   Qv[1]);
    __half2 h1 = __floats2half2_rn(Qv[2], Qv[3]);
    __half2 h2 = __floats2half2_rn(t11,   Qv[5]);
    __half2 h3 = __floats2half2_rn(Qv[6], Qv[7]);

    uint4 packed;
    packed.x = *reinterpret_cast<unsigned int*>(&h0);
    packed.y = *reinterpret_cast<unsigned int*>(&h1);
    packed.z = *reinterpret_cast<unsigned int*>(&h2);
    packed.w = *reinterpret_cast<unsigned int*>(&h3);
    reinterpret_cast<uint4*>(g_packed)[2 * u + 1] = packed;
}

__device__ __forceinline__ uint32_t smem_u32(const void* p) {
    uint32_t a;
    asm("{ .reg .u64 t; cvta.to.shared.u64 t, %1; cvt.u32.u64 %0, t; }"
        : "=r"(a) : "l"(p));
    return a;
}

__global__ void __launch_bounds__(BLK)
mlmm_pair_kernel(const float* __restrict__ dist,
                 const float* __restrict__ vec,
                 const float* __restrict__ outer,
                 const int* __restrict__ idx_u,
                 const int* __restrict__ idx_v,
                 const float* __restrict__ q_mm,
                 float* __restrict__ out,
                 int n) {
    __shared__ __align__(16) float s_vec[BLK * 3];   // 3072 B
    __shared__ __align__(16) float s_out[BLK * 9];   // 9216 B
    __shared__ __align__(8)  unsigned long long s_bar;

    long long base = (long long)blockIdx.x * BLK;
    int cnt = n - (int)base;
    if (cnt > BLK) cnt = BLK;

    int  lane    = threadIdx.x;
    bool fulltile = (cnt == BLK);

    uint32_t bar = smem_u32(&s_bar);

    // ---- init mbarrier (full tiles only) ----
    if (fulltile && lane == 0) {
        asm volatile("mbarrier.init.shared.b64 [%0], %1;"
                     :: "r"(bar), "r"(1u) : "memory");
    }
    __syncthreads();

    // ---- issue TMA bulk copies for vec/outer tiles (one thread) ----
    if (fulltile && lane == 0) {
        const unsigned tx_bytes = BLK * 12u * 4u;  // 12 floats/pair
        asm volatile("mbarrier.arrive.expect_tx.shared.b64 _, [%0], %1;"
                     :: "r"(bar), "r"(tx_bytes) : "memory");
        asm volatile(
            "cp.async.bulk.shared::cluster.global.mbarrier::complete_tx::bytes"
            " [%0], [%1], %2, [%3];"
            :: "r"(smem_u32(s_vec)), "l"(vec + 3 * base),
               "r"((unsigned)(BLK * 3 * 4)), "r"(bar) : "memory");
        asm volatile(
            "cp.async.bulk.shared::cluster.global.mbarrier::complete_tx::bytes"
            " [%0], [%1], %2, [%3];"
            :: "r"(smem_u32(s_out)), "l"(outer + 9 * base),
               "r"((unsigned)(BLK * 9 * 4)), "r"(bar) : "memory");
    }

    // ---- per-thread loads issued while TMA streams (R6 pipelining) ----
    long long i = base + lane;
    float d = 1e30f;
    if (lane < cnt) d = dist[i];
    bool m = (d <= CUTOFF_A);

    int u = 0, v = 0;
    if (m) { u = idx_u[i]; v = idx_v[i]; }

    float4 p0 = make_float4(0.f, 0.f, 0.f, 0.f);
    uint4  ph = make_uint4(0u, 0u, 0u, 0u);
    float  qv = 0.f;
    if (m) {
        p0 = g_packed[2 * u + 0];
        ph = reinterpret_cast<const uint4*>(g_packed)[2 * u + 1];
        qv = KE_CONST * __ldg(q_mm + v);
    }

    // ---- wait for tile data ----
    if (fulltile) {
        unsigned done;
        asm volatile(
            "{\n\t.reg .pred p;\n\t"
            "mbarrier.try_wait.parity.acquire.cta.shared::cta.b64 p, [%1], %2;\n\t"
            "selp.b32 %0, 1, 0, p;\n\t}"
            : "=r"(done) : "r"(bar), "r"(0u) : "memory");
        while (!done) {
            asm volatile(
                "{\n\t.reg .pred p;\n\t"
                "mbarrier.try_wait.parity.acquire.cta.shared::cta.b64 p, [%1], %2;\n\t"
                "selp.b32 %0, 1, 0, p;\n\t}"
                : "=r"(done) : "r"(bar), "r"(0u) : "memory");
        }
    } else {
        // tail fallback: scalar staging
        for (int t = threadIdx.x; t < cnt * 3; t += BLK) s_vec[t] = vec[3 * base + t];
        for (int t = threadIdx.x; t < cnt * 9; t += BLK) s_out[t] = outer[9 * base + t];
        __syncthreads();
    }

    if (!m) return;

    // ---- math + scatter ----
    float r0 = s_vec[3 * lane + 0];
    float r1 = s_vec[3 * lane + 1];
    float r2 = s_vec[3 * lane + 2];

    const float* op = s_out + 9 * lane;
    float o00 = op[0], o01 = op[1], o02 = op[2];
    float o10 = op[3], o11 = op[4], o12 = op[5];
    float o20 = op[6], o21 = op[7], o22 = op[8];

    float chi  = __fdividef(1.0f, d);
    float chi2 = chi * chi;
    float chi3 = chi2 * chi;
    float chi5 = chi3 * chi2;

    // charge-charge
    float e = p0.x * chi;

    // dipole: - chi^3 * (r . mu)
    e -= chi3 * (r0 * p0.y + r1 * p0.z + r2 * p0.w);

    // quadrupole: + chi^5 * sum(O * Q'), Q'22 = -(Q'00 + Q'11)
    float2 c0 = __half22float2(*reinterpret_cast<__half2*>(&ph.x)); // t00, Q01
    float2 c1 = __half22float2(*reinterpret_cast<__half2*>(&ph.y)); // Q02, Q10
    float2 c2 = __half22float2(*reinterpret_cast<__half2*>(&ph.z)); // t11, Q12
    float2 c3 = __half22float2(*reinterpret_cast<__half2*>(&ph.w)); // Q20, Q21

    float dot9 = c0.x * (o00 - o22)
               + c2.x * (o11 - o22)
               + c0.y * o01 + c1.x * o02 + c1.y * o10
               + c2.y * o12 + c3.x * o20 + c3.y * o21;
    e += chi5 * dot9;

    e *= qv;

    atomicAdd(out + u, e);
}

extern "C" void kernel_launch(void* const* d_in, const int* in_sizes, int n_in,
                              void* d_out, int out_size) {
    const float* q_ml  = (const float*)d_in[0];  // [NML]
    const float* q_mm  = (const float*)d_in[1];  // [NMM]
    const float* mu    = (const float*)d_in[2];  // [NML,3]
    const float* Q     = (const float*)d_in[3];  // [NML,3,3]
    const float* e0    = (const float*)d_in[4];  // [NML]
    const float* dist  = (const float*)d_in[5];  // [P]
    const float* vec   = (const float*)d_in[6];  // [P,3]
    const float* outer = (const float*)d_in[7];  // [P,3,3]
    const int*   idx_u = (const int*)d_in[8];    // [P] int32
    const int*   idx_v = (const int*)d_in[9];    // [P] int32

    float* out = (float*)d_out;

    int nml = in_sizes[0];
    int P   = in_sizes[5];

    {
        int threads = 256;
        int blocks  = (nml + threads - 1) / threads;
        mlmm_prep_kernel<<<blocks, threads>>>(q_ml, mu, Q, e0, out, nml);
    }
    {
        int blocks = (P + BLK - 1) / BLK;
        mlmm_pair_kernel<<<blocks, BLK>>>(dist, vec, outer, idx_u, idx_v,
                                          q_mm, out, P);
    }
}

// round 10
// speedup vs baseline: 1.1237x; 1.0948x over previous
#include <cuda_runtime.h>
#include <cuda_fp16.h>
#include <cstdint>

// ---------------------------------------------------------------------------
// MLMM electrostatics.
// E(p) = KE * q_v * ( q_u*chi - chi^3*(r.mu) + chi^5 * sum(O * Q') )
// with Q' = Q - (trQ/3) I (traceless), Q'22 = -(Q'00+Q'11).
//
// Gather record per ML atom: 32 bytes, 32B-aligned (ONE L2 sector):
//   float4 {q, mux, muy, muz} | 8 x fp16 {Q' components}
//
// R10 = R6 structure (proven 122us: 1 pair/thread, regs 32, LDG+STS staging,
// gathers issued before the staging barrier) plus:
//  - ONE ld.global.nc.v8.f32 (LDG.E.256, Blackwell) for the whole 32B record
//    instead of two LDG.128: halves the divergent-gather wavefront cost.
//  - idx_u/idx_v loaded unconditionally (coalesced lines are fetched anyway),
//    so they issue in parallel with dist instead of serially after the mask.
//  - KE folded into qv; int32 indexing throughout.
// ---------------------------------------------------------------------------

#define NML_MAX 50000
#define KE_CONST 14.399645351950548f
#define CUTOFF_A 10.0f
#define BLK 256

// [2*u] : float4 {q, mu}; [2*u+1] : 8 fp16 Q' components
__device__ __align__(32) float4 g_packed[NML_MAX * 2];

__global__ void mlmm_prep_kernel(const float* __restrict__ q_ml,
                                 const float* __restrict__ mu,
                                 const float* __restrict__ Q,
                                 const float* __restrict__ e0,
                                 float* __restrict__ out,
                                 int nml) {
    int u = blockIdx.x * blockDim.x + threadIdx.x;
    if (u >= nml) return;

    out[u] = e0[u];

    float m0 = mu[3 * u + 0];
    float m1 = mu[3 * u + 1];
    float m2 = mu[3 * u + 2];

    float Qv[9];
#pragma unroll
    for (int k = 0; k < 9; k++) Qv[k] = Q[9 * u + k];
    float third_tr = (Qv[0] + Qv[4] + Qv[8]) * (1.0f / 3.0f);

    float t00 = Qv[0] - third_tr;
    float t11 = Qv[4] - third_tr;

    g_packed[2 * u + 0] = make_float4(q_ml[u], m0, m1, m2);

    __half2 h0 = __floats2half2_rn(t00,   Qv[1]);
    __half2 h1 = __floats2half2_rn(Qv[2], Qv[3]);
    __half2 h2 = __floats2half2_rn(t11,   Qv[5]);
    __half2 h3 = __floats2half2_rn(Qv[6], Qv[7]);

    uint4 packed;
    packed.x = *reinterpret_cast<unsigned int*>(&h0);
    packed.y = *reinterpret_cast<unsigned int*>(&h1);
    packed.z = *reinterpret_cast<unsigned int*>(&h2);
    packed.w = *reinterpret_cast<unsigned int*>(&h3);
    reinterpret_cast<uint4*>(g_packed)[2 * u + 1] = packed;
}

__global__ void __launch_bounds__(BLK)
mlmm_pair_kernel(const float* __restrict__ dist,
                 const float* __restrict__ vec,
                 const float* __restrict__ outer,
                 const int* __restrict__ idx_u,
                 const int* __restrict__ idx_v,
                 const float* __restrict__ q_mm,
                 float* __restrict__ out,
                 int n) {
    __shared__ float s_vec[BLK * 3];
    __shared__ float s_out[BLK * 9];

    int base = blockIdx.x * BLK;      // P < 2^31: int math throughout
    int cnt  = n - base;
    if (cnt > BLK) cnt = BLK;

    int lane = threadIdx.x;
    int i    = base + lane;

    // ---- phase 1: per-thread loads, issued EARLY and in parallel ----
    float d = 1e30f;
    int   u = 0, v = 0;
    if (lane < cnt) {
        d = dist[i];
        u = idx_u[i];   // unconditional on mask: lines fetched by warp anyway
        v = idx_v[i];
    }
    bool m = (d <= CUTOFF_A);

    float4 p0 = make_float4(0.f, 0.f, 0.f, 0.f);
    uint4  ph = make_uint4(0u, 0u, 0u, 0u);
    float  qv = 0.f;
    if (m) {
        // single 256-bit gather of the whole 32B record (Blackwell LDG.E.256)
        const float* rec = reinterpret_cast<const float*>(g_packed + 2 * u);
        float f0, f1, f2, f3, f4, f5, f6, f7;
        asm volatile(
            "ld.global.nc.v8.f32 {%0, %1, %2, %3, %4, %5, %6, %7}, [%8];"
            : "=f"(f0), "=f"(f1), "=f"(f2), "=f"(f3),
              "=f"(f4), "=f"(f5), "=f"(f6), "=f"(f7)
            : "l"(rec));
        p0 = make_float4(f0, f1, f2, f3);
        ph = make_uint4(__float_as_uint(f4), __float_as_uint(f5),
                        __float_as_uint(f6), __float_as_uint(f7));
        qv = KE_CONST * __ldg(q_mm + v);
    }

    // ---- phase 2: stage vec/outer tiles (coalesced float4) ----
    if (cnt == BLK) {
        const float4* v4 = (const float4*)(vec + 3 * base);
        float4*       sv = (float4*)s_vec;
#pragma unroll
        for (int t = threadIdx.x; t < BLK * 3 / 4; t += BLK) sv[t] = v4[t];

        const float4* o4 = (const float4*)(outer + 9 * base);
        float4*       so = (float4*)s_out;
#pragma unroll
        for (int t = threadIdx.x; t < BLK * 9 / 4; t += BLK) so[t] = o4[t];
    } else {
        for (int t = threadIdx.x; t < cnt * 3; t += BLK) s_vec[t] = vec[3 * base + t];
        for (int t = threadIdx.x; t < cnt * 9; t += BLK) s_out[t] = outer[9 * base + t];
    }
    __syncthreads();

    if (!m) return;

    // ---- phase 3: math + scatter ----
    float r0 = s_vec[3 * lane + 0];
    float r1 = s_vec[3 * lane + 1];
    float r2 = s_vec[3 * lane + 2];

    const float* op = s_out + 9 * lane;
    float o00 = op[0], o01 = op[1], o02 = op[2];
    float o10 = op[3], o11 = op[4], o12 = op[5];
    float o20 = op[6], o21 = op[7], o22 = op[8];

    float chi  = __fdividef(1.0f, d);
    float chi2 = chi * chi;
    float chi3 = chi2 * chi;
    float chi5 = chi3 * chi2;

    // charge-charge
    float e = p0.x * chi;

    // dipole: - chi^3 * (r . mu)
    e -= chi3 * (r0 * p0.y + r1 * p0.z + r2 * p0.w);

    // quadrupole: + chi^5 * sum(O * Q'), Q'22 = -(Q'00 + Q'11)
    float2 c0 = __half22float2(*reinterpret_cast<__half2*>(&ph.x)); // t00, Q01
    float2 c1 = __half22float2(*reinterpret_cast<__half2*>(&ph.y)); // Q02, Q10
    float2 c2 = __half22float2(*reinterpret_cast<__half2*>(&ph.z)); // t11, Q12
    float2 c3 = __half22float2(*reinterpret_cast<__half2*>(&ph.w)); // Q20, Q21

    float dot9 = c0.x * (o00 - o22)
               + c2.x * (o11 - o22)
               + c0.y * o01 + c1.x * o02 + c1.y * o10
               + c2.y * o12 + c3.x * o20 + c3.y * o21;
    e += chi5 * dot9;

    e *= qv;

    atomicAdd(out + u, e);
}

extern "C" void kernel_launch(void* const* d_in, const int* in_sizes, int n_in,
                              void* d_out, int out_size) {
    const float* q_ml  = (const float*)d_in[0];  // [NML]
    const float* q_mm  = (const float*)d_in[1];  // [NMM]
    const float* mu    = (const float*)d_in[2];  // [NML,3]
    const float* Q     = (const float*)d_in[3];  // [NML,3,3]
    const float* e0    = (const float*)d_in[4];  // [NML]
    const float* dist  = (const float*)d_in[5];  // [P]
    const float* vec   = (const float*)d_in[6];  // [P,3]
    const float* outer = (const float*)d_in[7];  // [P,3,3]
    const int*   idx_u = (const int*)d_in[8];    // [P] int32
    const int*   idx_v = (const int*)d_in[9];    // [P] int32

    float* out = (float*)d_out;

    int nml = in_sizes[0];
    int P   = in_sizes[5];

    {
        int threads = 256;
        int blocks  = (nml + threads - 1) / threads;
        mlmm_prep_kernel<<<blocks, threads>>>(q_ml, mu, Q, e0, out, nml);
    }
    {
        int blocks = (P + BLK - 1) / BLK;
        mlmm_pair_kernel<<<blocks, BLK>>>(dist, vec, outer, idx_u, idx_v,
                                          q_mm, out, P);
    }
}

// round 11
// speedup vs baseline: 1.1991x; 1.0671x over previous
#include <cuda_runtime.h>
#include <cuda_fp16.h>
#include <cstdint>

// ---------------------------------------------------------------------------
// MLMM electrostatics.
// E(p) = KE * q_v * ( q_u*chi - chi^3*(r.mu) + chi^5 * sum(O * Q') )
// with Q' = Q - (trQ/3) I (traceless), Q'22 = -(Q'00+Q'11).
//
// Gather record per ML atom: 32 bytes, 32B-aligned (ONE L2 sector), fetched
// with a single Blackwell LDG.E.256 (ld.global.nc.v8.f32).
//
// R11 = R10 + warp-synchronous staging: each warp stages its own 32-pair
// vec/outer slice into a private smem chunk and proceeds after __syncwarp().
// No __syncthreads(): removes the 8-warp coupling where one straggling
// staging load stalled the whole block every tile.
// ---------------------------------------------------------------------------

#define NML_MAX 50000
#define KE_CONST 14.399645351950548f
#define CUTOFF_A 10.0f
#define BLK 256

// [2*u] : float4 {q, mu}; [2*u+1] : 8 fp16 Q' components
__device__ __align__(32) float4 g_packed[NML_MAX * 2];

__global__ void mlmm_prep_kernel(const float* __restrict__ q_ml,
                                 const float* __restrict__ mu,
                                 const float* __restrict__ Q,
                                 const float* __restrict__ e0,
                                 float* __restrict__ out,
                                 int nml) {
    int u = blockIdx.x * blockDim.x + threadIdx.x;
    if (u >= nml) return;

    out[u] = e0[u];

    float m0 = mu[3 * u + 0];
    float m1 = mu[3 * u + 1];
    float m2 = mu[3 * u + 2];

    float Qv[9];
#pragma unroll
    for (int k = 0; k < 9; k++) Qv[k] = Q[9 * u + k];
    float third_tr = (Qv[0] + Qv[4] + Qv[8]) * (1.0f / 3.0f);

    float t00 = Qv[0] - third_tr;
    float t11 = Qv[4] - third_tr;

    g_packed[2 * u + 0] = make_float4(q_ml[u], m0, m1, m2);

    __half2 h0 = __floats2half2_rn(t00,   Qv[1]);
    __half2 h1 = __floats2half2_rn(Qv[2], Qv[3]);
    __half2 h2 = __floats2half2_rn(t11,   Qv[5]);
    __half2 h3 = __floats2half2_rn(Qv[6], Qv[7]);

    uint4 packed;
    packed.x = *reinterpret_cast<unsigned int*>(&h0);
    packed.y = *reinterpret_cast<unsigned int*>(&h1);
    packed.z = *reinterpret_cast<unsigned int*>(&h2);
    packed.w = *reinterpret_cast<unsigned int*>(&h3);
    reinterpret_cast<uint4*>(g_packed)[2 * u + 1] = packed;
}

__global__ void __launch_bounds__(BLK)
mlmm_pair_kernel(const float* __restrict__ dist,
                 const float* __restrict__ vec,
                 const float* __restrict__ outer,
                 const int* __restrict__ idx_u,
                 const int* __restrict__ idx_v,
                 const float* __restrict__ q_mm,
                 float* __restrict__ out,
                 int n) {
    __shared__ float s_vec[BLK * 3];   // per-warp chunks of 96 floats
    __shared__ float s_out[BLK * 9];   // per-warp chunks of 288 floats

    int base = blockIdx.x * BLK;
    int cnt  = n - base;
    if (cnt > BLK) cnt = BLK;

    int tid  = threadIdx.x;
    int lane = tid & 31;
    int w    = tid >> 5;

    // ---- phase 1: per-thread loads, issued EARLY and in parallel ----
    int   i = base + tid;
    float d = 1e30f;
    int   u = 0, v = 0;
    if (tid < cnt) {
        d = dist[i];
        u = idx_u[i];   // unconditional: lines fetched by the warp anyway
        v = idx_v[i];
    }
    bool m = (d <= CUTOFF_A);

    float4 p0 = make_float4(0.f, 0.f, 0.f, 0.f);
    uint4  ph = make_uint4(0u, 0u, 0u, 0u);
    float  qv = 0.f;
    if (m) {
        // single 256-bit gather of the whole 32B record (Blackwell LDG.E.256)
        const float* rec = reinterpret_cast<const float*>(g_packed + 2 * u);
        float f0, f1, f2, f3, f4, f5, f6, f7;
        asm volatile(
            "ld.global.nc.v8.f32 {%0, %1, %2, %3, %4, %5, %6, %7}, [%8];"
            : "=f"(f0), "=f"(f1), "=f"(f2), "=f"(f3),
              "=f"(f4), "=f"(f5), "=f"(f6), "=f"(f7)
            : "l"(rec));
        p0 = make_float4(f0, f1, f2, f3);
        ph = make_uint4(__float_as_uint(f4), __float_as_uint(f5),
                        __float_as_uint(f6), __float_as_uint(f7));
        qv = KE_CONST * __ldg(q_mm + v);
    }

    // ---- phase 2: WARP-LOCAL staging of this warp's 32 pairs ----
    int wbase = base + 32 * w;       // first pair of this warp
    int wcnt  = cnt - 32 * w;        // pairs this warp owns
    if (wcnt > 32) wcnt = 32;

    float* sv = s_vec + 96 * w;      // 96 floats  (32 pairs x 3)
    float* so = s_out + 288 * w;     // 288 floats (32 pairs x 9)

    if (wcnt == 32) {
        // fully coalesced float4 staging; warp-chunk bases are 16B aligned
        const float4* v4 = (const float4*)(vec + 3 * wbase);
        if (lane < 24) reinterpret_cast<float4*>(sv)[lane] = v4[lane];

        const float4* o4 = (const float4*)(outer + 9 * wbase);
#pragma unroll
        for (int t = lane; t < 72; t += 32)
            reinterpret_cast<float4*>(so)[t] = o4[t];
    } else if (wcnt > 0) {
        for (int t = lane; t < wcnt * 3; t += 32) sv[t] = vec[3 * wbase + t];
        for (int t = lane; t < wcnt * 9; t += 32) so[t] = outer[9 * wbase + t];
    }
    __syncwarp();

    if (!m) return;

    // ---- phase 3: math + scatter ----
    float r0 = sv[3 * lane + 0];
    float r1 = sv[3 * lane + 1];
    float r2 = sv[3 * lane + 2];

    const float* op = so + 9 * lane;
    float o00 = op[0], o01 = op[1], o02 = op[2];
    float o10 = op[3], o11 = op[4], o12 = op[5];
    float o20 = op[6], o21 = op[7], o22 = op[8];

    float chi  = __fdividef(1.0f, d);
    float chi2 = chi * chi;
    float chi3 = chi2 * chi;
    float chi5 = chi3 * chi2;

    // charge-charge
    float e = p0.x * chi;

    // dipole: - chi^3 * (r . mu)
    e -= chi3 * (r0 * p0.y + r1 * p0.z + r2 * p0.w);

    // quadrupole: + chi^5 * sum(O * Q'), Q'22 = -(Q'00 + Q'11)
    float2 c0 = __half22float2(*reinterpret_cast<__half2*>(&ph.x)); // t00, Q01
    float2 c1 = __half22float2(*reinterpret_cast<__half2*>(&ph.y)); // Q02, Q10
    float2 c2 = __half22float2(*reinterpret_cast<__half2*>(&ph.z)); // t11, Q12
    float2 c3 = __half22float2(*reinterpret_cast<__half2*>(&ph.w)); // Q20, Q21

    float dot9 = c0.x * (o00 - o22)
               + c2.x * (o11 - o22)
               + c0.y * o01 + c1.x * o02 + c1.y * o10
               + c2.y * o12 + c3.x * o20 + c3.y * o21;
    e += chi5 * dot9;

    e *= qv;

    atomicAdd(out + u, e);
}

extern "C" void kernel_launch(void* const* d_in, const int* in_sizes, int n_in,
                              void* d_out, int out_size) {
    const float* q_ml  = (const float*)d_in[0];  // [NML]
    const float* q_mm  = (const float*)d_in[1];  // [NMM]
    const float* mu    = (const float*)d_in[2];  // [NML,3]
    const float* Q     = (const float*)d_in[3];  // [NML,3,3]
    const float* e0    = (const float*)d_in[4];  // [NML]
    const float* dist  = (const float*)d_in[5];  // [P]
    const float* vec   = (const float*)d_in[6];  // [P,3]
    const float* outer = (const float*)d_in[7];  // [P,3,3]
    const int*   idx_u = (const int*)d_in[8];    // [P] int32
    const int*   idx_v = (const int*)d_in[9];    // [P] int32

    float* out = (float*)d_out;

    int nml = in_sizes[0];
    int P   = in_sizes[5];

    {
        int threads = 256;
        int blocks  = (nml + threads - 1) / threads;
        mlmm_prep_kernel<<<blocks, threads>>>(q_ml, mu, Q, e0, out, nml);
    }
    {
        int blocks = (P + BLK - 1) / BLK;
        mlmm_pair_kernel<<<blocks, BLK>>>(dist, vec, outer, idx_u, idx_v,
                                          q_mm, out, P);
    }
}